// round 6
// baseline (speedup 1.0000x reference)
#include <cuda_runtime.h>

// Problem constants
#define BB    128
#define TT    32
#define DD    128
#define NSLOT 128
#define BITS  32
#define HH    4
#define UU    256
#define HDW   128
#define CTLW  256
#define OUTW  384
#define MPITCH 36
#define THREADS 768
#define NB    2                    // batches per CTA

// Weight pinning in shared memory
#define RC_PIN 80
#define RF_PIN 32
#define PIN_WC (RC_PIN * UU)       // 20480 floats
#define PIN_WF (RF_PIN * OUTW)     // 12288 floats
#define REDN   6144                // split-k scratch (2 batches), aliases logits

struct SmemLayout {
    float M[NB][NSLOT * MPITCH];   // 9216
    float ctl[NB][CTLW];
    float hctl[NB][UU];
    float o[NB][OUTW];
    float rW[NB][HH * NSLOT];
    float wW[NB][HH * NSLOT];
    float hisW[NB][HH * NSLOT];
    float rv[NB][HDW];
    float minv[NB][NSLOT];
    float kinv[NB][HH];
    float kinvw[NB][HH];
    float beta_s[HH * NSLOT];
    float g_s[HH * NSLOT];
    float Wg_s[NB][HH * NSLOT];
    float er_s[NB][HH * BITS];
    float ad_s[NB][HH * BITS];
    float bc_s[UU];
    float bf_s[OUTW];
    float red[REDN];               // P2/P7 logits alias red[0..1023]
    float wpinC[PIN_WC];
    float wpinF[PIN_WF];
};
// 56,720 floats = 226,880 bytes <= 227 KB opt-in

// dual-batch logits: e_bi[h,n] = -beta[h,n]*kinv[bi][h]*minv[bi][n]*(key_bi_h . M_bi_n)
__device__ __forceinline__ void sim_logits2(SmemLayout* s,
                                            const float (*keys)[HDW] ,
                                            const float (*kinvv)[HH], int tid)
{
    if (tid < HH * NSLOT) {
        int h = tid >> 7, n = tid & 127;
        float bsc = s->beta_s[tid];
#pragma unroll
        for (int bi = 0; bi < NB; ++bi) {
            const float4* Mr = reinterpret_cast<const float4*>(&s->M[bi][n * MPITCH]);
            const float4* Kr = reinterpret_cast<const float4*>(&keys[bi][h * BITS]);
            float raw = 0.f;
#pragma unroll
            for (int i = 0; i < 8; ++i) {
                float4 mm = Mr[i];
                float4 kk = Kr[i];
                raw += mm.x * kk.x + mm.y * kk.y + mm.z * kk.z + mm.w * kk.w;
            }
            s->red[bi * 512 + tid] = -bsc * kinvv[bi][h] * s->minv[bi][n] * raw;
        }
    }
}

// warp softmax-blend: warps 0-3 => batch0 heads, warps 4-7 => batch1 heads
__device__ __forceinline__ void softmax_blend2(SmemLayout* s, float (*dst)[HH * NSLOT],
                                               int warp, int lane)
{
    if (warp < 2 * HH) {
        int bi = warp >> 2, h = warp & 3;
        const float* e = &s->red[bi * 512];
        float v[4];
#pragma unroll
        for (int i = 0; i < 4; ++i) v[i] = e[h * NSLOT + lane + i * 32];
        float m = fmaxf(fmaxf(v[0], v[1]), fmaxf(v[2], v[3]));
#pragma unroll
        for (int off = 16; off > 0; off >>= 1) m = fmaxf(m, __shfl_xor_sync(0xffffffffu, m, off));
        float sum = 0.f;
#pragma unroll
        for (int i = 0; i < 4; ++i) { v[i] = __expf(v[i] - m); sum += v[i]; }
#pragma unroll
        for (int off = 16; off > 0; off >>= 1) sum += __shfl_xor_sync(0xffffffffu, sum, off);
        float inv = 1.0f / sum;
#pragma unroll
        for (int i = 0; i < 4; ++i) {
            int n = lane + i * 32;
            float gg = s->g_s[h * NSLOT + n];
            dst[bi][h * NSLOT + n] = gg * (v[i] * inv) + (1.f - gg) * dst[bi][h * NSLOT + n];
        }
    }
}

__global__ __launch_bounds__(THREADS, 1)
void uic_kernel(const float* __restrict__ x, const float* __restrict__ beta,
                const float* __restrict__ g, const float* __restrict__ erase,
                const float* __restrict__ add, const float* __restrict__ Wg,
                const float* __restrict__ M0, const float* __restrict__ read0,
                const float* __restrict__ readW0, const float* __restrict__ writeW0,
                const float* __restrict__ Wc, const float* __restrict__ bc,
                const float* __restrict__ Wf, const float* __restrict__ bf,
                float* __restrict__ out)
{
    extern __shared__ float smem_raw[];
    SmemLayout* s = reinterpret_cast<SmemLayout*>(smem_raw);
    const int b0 = blockIdx.x * NB;
    const int tid = threadIdx.x;
    const int lane = tid & 31;
    const int warp = tid >> 5;

    // ---------------- init ----------------
    for (int p = tid; p < NB * NSLOT * BITS; p += THREADS) {
        int bi = p >> 12, idx = p & 4095;
        int n = idx >> 5, d = idx & 31;
        s->M[bi][n * MPITCH + d] = M0[(b0 + bi) * NSLOT * BITS + idx];
    }
    for (int p = tid; p < NB * HH * NSLOT; p += THREADS) {
        int bi = p >> 9, idx = p & 511;
        s->rW[bi][idx]   = readW0[(b0 + bi) * HH * NSLOT + idx];
        s->wW[bi][idx]   = writeW0[(b0 + bi) * HH * NSLOT + idx];
        s->hisW[bi][idx] = 0.f;
        s->Wg_s[bi][idx] = Wg[(b0 + bi) * HH * NSLOT + idx];
    }
    for (int idx = tid; idx < HH * NSLOT; idx += THREADS) {
        s->beta_s[idx] = beta[idx];
        s->g_s[idx]    = g[idx];
    }
    for (int p = tid; p < NB * HDW; p += THREADS) {
        int bi = p >> 7, idx = p & 127;
        s->rv[bi][idx]   = read0[(b0 + bi) * HDW + idx];
        s->er_s[bi][idx] = erase[(b0 + bi) * HDW + idx];
        s->ad_s[bi][idx] = add[(b0 + bi) * HDW + idx];
    }
    for (int idx = tid; idx < UU; idx += THREADS)   s->bc_s[idx] = bc[idx];
    for (int idx = tid; idx < OUTW; idx += THREADS) s->bf_s[idx] = bf[idx];
    for (int idx = tid; idx < PIN_WC; idx += THREADS) s->wpinC[idx] = Wc[idx];
    for (int idx = tid; idx < PIN_WF; idx += THREADS) s->wpinF[idx] = Wf[idx];
    __syncthreads();

    // ---------------- prologue: x(t=0), minv, kinv ----------------
    if (tid < NB * DD) {
        int bi = tid >> 7, d = tid & 127;
        s->ctl[bi][d] = x[(b0 + bi) * TT * DD + d];
    } else if (tid < NB * DD + NB * NSLOT) {
        int p = tid - NB * DD;
        int bi = p >> 7, n = p & 127;
        const float4* Mr = reinterpret_cast<const float4*>(&s->M[bi][n * MPITCH]);
        float ss = 0.f;
#pragma unroll
        for (int i = 0; i < 8; ++i) {
            float4 v = Mr[i];
            ss += v.x * v.x + v.y * v.y + v.z * v.z + v.w * v.w;
        }
        s->minv[bi][n] = rsqrtf(fmaxf(ss, 1e-12f));
    } else if (tid < NB * DD + NB * NSLOT + NB * HH) {
        int p = tid - (NB * DD + NB * NSLOT);
        int bi = p >> 2, h = p & 3;
        float ss = 0.f;
#pragma unroll
        for (int k = 0; k < BITS; ++k) { float v = s->rv[bi][h * BITS + k]; ss += v * v; }
        s->kinv[bi][h] = rsqrtf(fmaxf(ss, 1e-12f));
    }
    __syncthreads();

    static const int P3S[4] = {0, 43, 86, 128};

    for (int t = 0; t < TT; ++t) {
        // ---- P2: read-addressing logits (both batches) ----
        sim_logits2(s, s->rv, s->kinv, tid);
        __syncthreads();
        softmax_blend2(s, s->rW, warp, lane);
        __syncthreads();

        // ---- P3: read_input[bi][h,d], 3-way split-k per batch ----
        {
            int grp = tid / 128;          // 0..5
            int idx = tid & 127;
            int bi = grp / 3, seg = grp - bi * 3;
            int h = idx >> 5, d = idx & 31;
            const float* rw = &s->rW[bi][h * NSLOT];
            const float* Mb = s->M[bi];
            float a = 0.f;
            int n0 = P3S[seg], n1 = P3S[seg + 1];
#pragma unroll 4
            for (int n = n0; n < n1; ++n) a += rw[n] * Mb[n * MPITCH + d];
            s->red[grp * 128 + idx] = a;
        }
        __syncthreads();
        if (tid < NB * HDW) {
            int bi = tid >> 7, idx = tid & 127;
            s->ctl[bi][DD + idx] = s->red[bi * 384 + idx] + s->red[bi * 384 + 128 + idx]
                                 + s->red[bi * 384 + 256 + idx];
        }
        __syncthreads();

        // ---- P4: hctl partials, 12 grp x 64 thr; w loaded once, 2 FMAs ----
        {
            int grp = tid >> 6;           // 0..11
            int u4  = (tid & 63) * 4;
            float4 a0 = make_float4(0.f, 0.f, 0.f, 0.f);
            float4 a1 = make_float4(0.f, 0.f, 0.f, 0.f);
            const float* c0 = s->ctl[0];
            const float* c1 = s->ctl[1];
            if (grp < 4) {                // pinned: 20 rows each (80 total)
                int k0 = grp * 20;
#pragma unroll 5
                for (int k = k0; k < k0 + 20; ++k) {
                    float4 w = *reinterpret_cast<const float4*>(&s->wpinC[k * UU + u4]);
                    float v0 = c0[k], v1 = c1[k];
                    a0.x += v0 * w.x; a0.y += v0 * w.y; a0.z += v0 * w.z; a0.w += v0 * w.w;
                    a1.x += v1 * w.x; a1.y += v1 * w.y; a1.z += v1 * w.z; a1.w += v1 * w.w;
                }
            } else {                      // streamed: 22 rows each (176 total)
                int k0 = RC_PIN + (grp - 4) * 22;
#pragma unroll 11
                for (int k = k0; k < k0 + 22; ++k) {
                    float4 w = __ldg(reinterpret_cast<const float4*>(&Wc[k * UU + u4]));
                    float v0 = c0[k], v1 = c1[k];
                    a0.x += v0 * w.x; a0.y += v0 * w.y; a0.z += v0 * w.z; a0.w += v0 * w.w;
                    a1.x += v1 * w.x; a1.y += v1 * w.y; a1.z += v1 * w.z; a1.w += v1 * w.w;
                }
            }
            *reinterpret_cast<float4*>(&s->red[grp * UU + u4]) = a0;
            *reinterpret_cast<float4*>(&s->red[3072 + grp * UU + u4]) = a1;
        }
        __syncthreads();
        if (tid < NB * UU) {
            int bi = tid >> 8, u = tid & 255;
            float a = s->bc_s[u];
            const float* rp = &s->red[bi * 3072];
#pragma unroll
            for (int grp = 0; grp < 12; ++grp) a += rp[grp * UU + u];
            s->hctl[bi][u] = fmaxf(a, 0.f);
        }
        __syncthreads();

        // ---- P5: o partials, 8 grp x 96 thr; w loaded once, 2 FMAs ----
        {
            int grp = tid / 96;           // 0..7
            int v4  = (tid - grp * 96) * 4;
            float4 a0 = make_float4(0.f, 0.f, 0.f, 0.f);
            float4 a1 = make_float4(0.f, 0.f, 0.f, 0.f);
            const float* h0 = s->hctl[0];
            const float* h1 = s->hctl[1];
            if (grp == 0) {               // pinned: 32 rows
#pragma unroll 8
                for (int k = 0; k < RF_PIN; ++k) {
                    float4 w = *reinterpret_cast<const float4*>(&s->wpinF[k * OUTW + v4]);
                    float v0 = h0[k], v1 = h1[k];
                    a0.x += v0 * w.x; a0.y += v0 * w.y; a0.z += v0 * w.z; a0.w += v0 * w.w;
                    a1.x += v1 * w.x; a1.y += v1 * w.y; a1.z += v1 * w.z; a1.w += v1 * w.w;
                }
            } else {                      // streamed: 32 rows each (224 total)
                int k0 = RF_PIN + (grp - 1) * 32;
#pragma unroll 8
                for (int k = k0; k < k0 + 32; ++k) {
                    float4 w = __ldg(reinterpret_cast<const float4*>(&Wf[k * OUTW + v4]));
                    float v0 = h0[k], v1 = h1[k];
                    a0.x += v0 * w.x; a0.y += v0 * w.y; a0.z += v0 * w.z; a0.w += v0 * w.w;
                    a1.x += v1 * w.x; a1.y += v1 * w.y; a1.z += v1 * w.z; a1.w += v1 * w.w;
                }
            }
            *reinterpret_cast<float4*>(&s->red[grp * OUTW + v4]) = a0;
            *reinterpret_cast<float4*>(&s->red[3072 + grp * OUTW + v4]) = a1;
        }
        __syncthreads();

        // ---- P5-reduce + P6: emit out / rv / write-keys / kinvw ----
        {
            int bi = tid / 384;
            int v  = tid - bi * 384;
            float a = s->bf_s[v];
            const float* rp = &s->red[bi * 3072];
#pragma unroll
            for (int grp = 0; grp < 8; ++grp) a += rp[grp * OUTW + v];
            if (v < DD) {
                out[(b0 + bi) * TT * DD + t * DD + v] = a;
            } else if (v < CTLW) {
                s->rv[bi][v - DD] = a;
            } else {
                s->o[bi][v] = a;
                // each warp here holds exactly one (bi, h) group of 32 values
                float ss = a * a;
#pragma unroll
                for (int off = 16; off > 0; off >>= 1) ss += __shfl_xor_sync(0xffffffffu, ss, off);
                if (lane == 0) s->kinvw[bi][(v - CTLW) >> 5] = rsqrtf(fmaxf(ss, 1e-12f));
            }
        }
        __syncthreads();

        // ---- P7: write addressing (old M; minv still valid) ----
        if (tid < HH * NSLOT) {
            int h = tid >> 7, n = tid & 127;
            float bsc = s->beta_s[tid];
#pragma unroll
            for (int bi = 0; bi < NB; ++bi) {
                const float4* Mr = reinterpret_cast<const float4*>(&s->M[bi][n * MPITCH]);
                const float4* Kr = reinterpret_cast<const float4*>(&s->o[bi][CTLW + h * BITS]);
                float raw = 0.f;
#pragma unroll
                for (int i = 0; i < 8; ++i) {
                    float4 mm = Mr[i];
                    float4 kk = Kr[i];
                    raw += mm.x * kk.x + mm.y * kk.y + mm.z * kk.z + mm.w * kk.w;
                }
                s->red[bi * 512 + tid] = -bsc * s->kinvw[bi][h] * s->minv[bi][n] * raw;
            }
        }
        __syncthreads();
        softmax_blend2(s, s->wW, warp, lane);
        __syncthreads();

        // ---- P8: M update with pre-Pt writeW (both batches) ----
        for (int p = tid; p < NB * NSLOT * BITS; p += THREADS) {
            int bi = p >> 12, idx = p & 4095;
            int n = idx >> 5, d = idx & 31;
            float ew = 0.f, aw = 0.f;
#pragma unroll
            for (int h = 0; h < HH; ++h) {
                float w = s->wW[bi][h * NSLOT + n];
                ew += w * s->er_s[bi][h * BITS + d];
                aw += w * s->ad_s[bi][h * BITS + d];
            }
            float mv = s->M[bi][n * MPITCH + d];
            s->M[bi][n * MPITCH + d] = mv * (1.f - ew) + aw;
        }
        __syncthreads();

        // ---- PF: P9 (warps 0-7) | M norms (256-511) | x prefetch + kinv (512-767) ----
        if (warp < 2 * HH) {
            int bi = warp >> 2, h = warp & 3;
            float v[4];
#pragma unroll
            for (int i = 0; i < 4; ++i) {
                int n = lane + i * 32;
                v[i] = s->Wg_s[bi][h * NSLOT + n] * s->hisW[bi][h * NSLOT + n];
            }
            float m = fmaxf(fmaxf(v[0], v[1]), fmaxf(v[2], v[3]));
#pragma unroll
            for (int off = 16; off > 0; off >>= 1) m = fmaxf(m, __shfl_xor_sync(0xffffffffu, m, off));
            float sum = 0.f;
#pragma unroll
            for (int i = 0; i < 4; ++i) { v[i] = __expf(v[i] - m); sum += v[i]; }
#pragma unroll
            for (int off = 16; off > 0; off >>= 1) sum += __shfl_xor_sync(0xffffffffu, sum, off);
            float inv = 1.0f / sum;
#pragma unroll
            for (int i = 0; i < 4; ++i) {
                int n = lane + i * 32;
                float wnew = s->wW[bi][h * NSLOT + n] * (v[i] * inv);
                s->wW[bi][h * NSLOT + n] = wnew;
                s->hisW[bi][h * NSLOT + n] += wnew;
            }
        } else if (tid < 512) {
            int p = tid - 256;
            int bi = p >> 7, n = p & 127;
            const float4* Mr = reinterpret_cast<const float4*>(&s->M[bi][n * MPITCH]);
            float ss = 0.f;
#pragma unroll
            for (int i = 0; i < 8; ++i) {
                float4 v = Mr[i];
                ss += v.x * v.x + v.y * v.y + v.z * v.z + v.w * v.w;
            }
            s->minv[bi][n] = rsqrtf(fmaxf(ss, 1e-12f));
        } else {
            int p = tid - 512;
            int bi = p >> 7, d = p & 127;
            if (t + 1 < TT) s->ctl[bi][d] = x[(b0 + bi) * TT * DD + (t + 1) * DD + d];
            if (p < NB * HH) {
                int kb = p >> 2, kh = p & 3;
                float ss = 0.f;
#pragma unroll
                for (int k = 0; k < BITS; ++k) { float v = s->rv[kb][kh * BITS + k]; ss += v * v; }
                s->kinv[kb][kh] = rsqrtf(fmaxf(ss, 1e-12f));
            }
        }
        __syncthreads();
    }
}

extern "C" void kernel_launch(void* const* d_in, const int* in_sizes, int n_in,
                              void* d_out, int out_size)
{
    const float* x       = (const float*)d_in[0];
    const float* beta    = (const float*)d_in[1];
    const float* g       = (const float*)d_in[2];
    const float* erase   = (const float*)d_in[3];
    const float* add     = (const float*)d_in[4];
    const float* Wg      = (const float*)d_in[5];
    const float* M0      = (const float*)d_in[6];
    const float* read0   = (const float*)d_in[7];
    const float* readW0  = (const float*)d_in[8];
    const float* writeW0 = (const float*)d_in[9];
    // d_in[10] = S0   (dead)
    const float* Wc      = (const float*)d_in[11];
    const float* bc      = (const float*)d_in[12];
    const float* Wf      = (const float*)d_in[13];
    const float* bf      = (const float*)d_in[14];
    // d_in[15..17] = Wi, Ui, b_gru (dead)

    (void)in_sizes; (void)n_in; (void)out_size;

    cudaFuncSetAttribute(uic_kernel, cudaFuncAttributeMaxDynamicSharedMemorySize,
                         (int)sizeof(SmemLayout));
    uic_kernel<<<BB / NB, THREADS, sizeof(SmemLayout)>>>(x, beta, g, erase, add, Wg,
                                                         M0, read0, readW0, writeW0,
                                                         Wc, bc, Wf, bf, (float*)d_out);
}

// round 7
// speedup vs baseline: 1.2716x; 1.2716x over previous
#include <cuda_runtime.h>
#include <cooperative_groups.h>

namespace cg = cooperative_groups;

// Problem constants
#define BB    128
#define TT    32
#define DD    128
#define NSLOT 128
#define BITS  32
#define HH    4
#define UU    256
#define HDW   128
#define CTLW  256
#define OUTW  384
#define MPITCH 36
#define THREADS 768
#define CHALF 128      // Wc column half per CTA
#define FHALF 192      // Wf column half per CTA
#define RFP   32       // pinned Wf rows (of 256)

struct SmemLayout {
    float M[NSLOT * MPITCH];     // 4608
    float ctlX[2][CTLW];         // ctl for both batches of the pair (bi = batch-in-pair)
    float hctlX[2][UU];          // full hidden for both batches (assembled via DSMEM)
    float o_half[2][FHALF];      // my column-half of o, both batches
    float o_full[OUTW];          // full o for MY batch
    float rW[HH * NSLOT];
    float wW[HH * NSLOT];
    float hisW[HH * NSLOT];
    float rv[HDW];
    float minv[NSLOT];
    float kinv[HH];
    float kinvw[HH];
    float beta_s[HH * NSLOT];
    float g_s[HH * NSLOT];
    float Wg_s[HH * NSLOT];
    float er_s[HH * BITS];
    float ad_s[HH * BITS];
    float bc_s[CHALF];           // my col-half of bc
    float bf_s[FHALF];           // my col-half of bf
    float red[6144];             // split-k scratch; aliases logits red[0..511]
    float wpinC[256 * CHALF];    // 32768: ALL Wc rows, my col-half
    float wpinF[RFP * FHALF];    // 6144:  Wf rows [0,RFP), my col-half
};
// 55,368 floats = 221,472 bytes < 232,448 B opt-in

// single-batch cosine logits into red[0..511]
__device__ __forceinline__ void sim_logits(SmemLayout* s, const float* __restrict__ keys,
                                           const float* __restrict__ kinvv, int tid)
{
    if (tid < HH * NSLOT) {
        int h = tid >> 7, n = tid & 127;
        const float4* Mr = reinterpret_cast<const float4*>(&s->M[n * MPITCH]);
        const float4* Kr = reinterpret_cast<const float4*>(&keys[h * BITS]);
        float raw = 0.f;
#pragma unroll
        for (int i = 0; i < 8; ++i) {
            float4 mm = Mr[i];
            float4 kk = Kr[i];
            raw += mm.x * kk.x + mm.y * kk.y + mm.z * kk.z + mm.w * kk.w;
        }
        s->red[tid] = -s->beta_s[tid] * kinvv[h] * s->minv[n] * raw;
    }
}

// warp softmax-blend over a head row (warps 0-3)
__device__ __forceinline__ void softmax_blend_row(SmemLayout* s, float* __restrict__ dst,
                                                  int h, int lane)
{
    float v[4];
#pragma unroll
    for (int i = 0; i < 4; ++i) v[i] = s->red[h * NSLOT + lane + i * 32];
    float m = fmaxf(fmaxf(v[0], v[1]), fmaxf(v[2], v[3]));
#pragma unroll
    for (int off = 16; off > 0; off >>= 1) m = fmaxf(m, __shfl_xor_sync(0xffffffffu, m, off));
    float sum = 0.f;
#pragma unroll
    for (int i = 0; i < 4; ++i) { v[i] = __expf(v[i] - m); sum += v[i]; }
#pragma unroll
    for (int off = 16; off > 0; off >>= 1) sum += __shfl_xor_sync(0xffffffffu, sum, off);
    float inv = 1.0f / sum;
#pragma unroll
    for (int i = 0; i < 4; ++i) {
        int n = lane + i * 32;
        float gg = s->g_s[h * NSLOT + n];
        dst[h * NSLOT + n] = gg * (v[i] * inv) + (1.f - gg) * dst[h * NSLOT + n];
    }
}

__global__ __cluster_dims__(2, 1, 1) __launch_bounds__(THREADS, 1)
void uic_kernel(const float* __restrict__ x, const float* __restrict__ beta,
                const float* __restrict__ g, const float* __restrict__ erase,
                const float* __restrict__ add, const float* __restrict__ Wg,
                const float* __restrict__ M0, const float* __restrict__ read0,
                const float* __restrict__ readW0, const float* __restrict__ writeW0,
                const float* __restrict__ Wc, const float* __restrict__ bc,
                const float* __restrict__ Wf, const float* __restrict__ bf,
                float* __restrict__ out)
{
    extern __shared__ float smem_raw[];
    SmemLayout* s = reinterpret_cast<SmemLayout*>(smem_raw);
    cg::cluster_group cl = cg::this_cluster();
    const int r    = (int)cl.block_rank();   // 0 or 1 within pair
    const int peer = r ^ 1;
    const int b    = blockIdx.x;             // my batch (CTA owns one batch's state)
    const int tid  = threadIdx.x;
    const int lane = tid & 31;
    const int warp = tid >> 5;

    // ---------------- init ----------------
    for (int idx = tid; idx < NSLOT * BITS; idx += THREADS) {
        int n = idx >> 5, d = idx & 31;
        s->M[n * MPITCH + d] = M0[b * NSLOT * BITS + idx];
    }
    for (int idx = tid; idx < HH * NSLOT; idx += THREADS) {
        s->rW[idx]     = readW0[b * HH * NSLOT + idx];
        s->wW[idx]     = writeW0[b * HH * NSLOT + idx];
        s->hisW[idx]   = 0.f;
        s->beta_s[idx] = beta[idx];
        s->g_s[idx]    = g[idx];
        s->Wg_s[idx]   = Wg[b * HH * NSLOT + idx];
    }
    for (int idx = tid; idx < HDW; idx += THREADS) {
        s->rv[idx]   = read0[b * HDW + idx];
        s->er_s[idx] = erase[b * HDW + idx];
        s->ad_s[idx] = add[b * HDW + idx];
    }
    for (int idx = tid; idx < CHALF; idx += THREADS) s->bc_s[idx] = bc[r * CHALF + idx];
    for (int idx = tid; idx < FHALF; idx += THREADS) s->bf_s[idx] = bf[r * FHALF + idx];
    // pin my column-half of ALL Wc rows, and Wf rows [0,RFP)
    for (int idx = tid; idx < 256 * CHALF; idx += THREADS) {
        int n = idx >> 7, c = idx & (CHALF - 1);
        s->wpinC[idx] = Wc[n * UU + r * CHALF + c];
    }
    for (int idx = tid; idx < RFP * FHALF; idx += THREADS) {
        int n = idx / FHALF, c = idx - n * FHALF;
        s->wpinF[idx] = Wf[n * OUTW + r * FHALF + c];
    }
    __syncthreads();

    // ---------------- prologue: x(t=0), minv, kinv ----------------
    if (tid < DD) {
        s->ctlX[r][tid] = x[b * TT * DD + tid];
    } else if (tid < 2 * NSLOT) {
        int n = tid - NSLOT;
        const float4* Mr = reinterpret_cast<const float4*>(&s->M[n * MPITCH]);
        float ss = 0.f;
#pragma unroll
        for (int i = 0; i < 8; ++i) {
            float4 v = Mr[i];
            ss += v.x * v.x + v.y * v.y + v.z * v.z + v.w * v.w;
        }
        s->minv[n] = rsqrtf(fmaxf(ss, 1e-12f));
    } else if (tid < 2 * NSLOT + HH) {
        int h = tid - 2 * NSLOT;
        float ss = 0.f;
#pragma unroll
        for (int k = 0; k < BITS; ++k) { float v = s->rv[h * BITS + k]; ss += v * v; }
        s->kinv[h] = rsqrtf(fmaxf(ss, 1e-12f));
    }
    __syncthreads();

    static const int P3S[7] = {0, 22, 44, 65, 86, 107, 128};

    for (int t = 0; t < TT; ++t) {
        // ---- P2: read addressing (local batch) ----
        sim_logits(s, s->rv, s->kinv, tid);
        __syncthreads();
        if (warp < HH) softmax_blend_row(s, s->rW, warp, lane);
        __syncthreads();

        // ---- P3: read_input = rW @ M, 6-way split-k ----
        {
            int grp = tid / 128;
            int idx = tid & 127;
            int h = idx >> 5, d = idx & 31;
            const float* rw = &s->rW[h * NSLOT];
            float a = 0.f;
            int n0 = P3S[grp], n1 = P3S[grp + 1];
#pragma unroll 4
            for (int n = n0; n < n1; ++n) a += rw[n] * s->M[n * MPITCH + d];
            s->red[grp * 128 + idx] = a;
        }
        __syncthreads();
        if (tid < HDW) {
            float a = 0.f;
#pragma unroll
            for (int grp = 0; grp < 6; ++grp) a += s->red[grp * 128 + tid];
            s->ctlX[r][DD + tid] = a;
        }
        __syncthreads();

        // ---- S1: exchange ctl (partner's full ctl -> my ctlX[peer]) ----
        cl.sync();
        if (tid < CTLW / 4) {
            const float4* src = (const float4*)cl.map_shared_rank((void*)s->ctlX[peer], peer);
            reinterpret_cast<float4*>(s->ctlX[peer])[tid] = src[tid];
        }
        __syncthreads();

        // ---- P4: hctl col-half for BOTH batches; Wc fully pinned ----
        {
            int seg = tid >> 5;                  // 0..23
            int c4  = tid & 31;                  // col4 within my half (32 float4 = 128 cols)
            int n0 = (256 * seg) / 24, n1 = (256 * (seg + 1)) / 24;
            float4 a0 = make_float4(0.f, 0.f, 0.f, 0.f);
            float4 a1 = make_float4(0.f, 0.f, 0.f, 0.f);
            const float4* wp = reinterpret_cast<const float4*>(s->wpinC);
            const float* c0 = s->ctlX[0];
            const float* c1 = s->ctlX[1];
            for (int n = n0; n < n1; ++n) {
                float4 w = wp[n * 32 + c4];
                float v0 = c0[n], v1 = c1[n];
                a0.x += v0 * w.x; a0.y += v0 * w.y; a0.z += v0 * w.z; a0.w += v0 * w.w;
                a1.x += v1 * w.x; a1.y += v1 * w.y; a1.z += v1 * w.z; a1.w += v1 * w.w;
            }
            float4* rd = reinterpret_cast<float4*>(s->red);
            rd[seg * 64 + c4]      = a0;
            rd[seg * 64 + 32 + c4] = a1;
        }
        __syncthreads();
        if (tid < 2 * CHALF) {
            int bi = tid >> 7, u = tid & 127;
            float a = s->bc_s[u];
#pragma unroll
            for (int seg = 0; seg < 24; ++seg) a += s->red[(seg * 64 + bi * 32) * 4 + u];
            s->hctlX[bi][r * CHALF + u] = fmaxf(a, 0.f);
        }
        __syncthreads();

        // ---- S2: exchange hctl halves ----
        cl.sync();
        if (tid < 64) {
            int bi = tid >> 5, q = tid & 31;
            const float4* src = (const float4*)cl.map_shared_rank(
                (void*)&s->hctlX[bi][peer * CHALF], peer);
            reinterpret_cast<float4*>(&s->hctlX[bi][peer * CHALF])[q] = src[q];
        }
        __syncthreads();

        // ---- P5: o col-half for BOTH batches; Wf rows 0..31 pinned, rest streamed ----
        {
            int seg = tid / 48;                  // 0..15, 16 rows each
            int c4  = tid - seg * 48;            // col4 within my half (48 float4 = 192 cols)
            float4 a0 = make_float4(0.f, 0.f, 0.f, 0.f);
            float4 a1 = make_float4(0.f, 0.f, 0.f, 0.f);
            const float* h0 = s->hctlX[0];
            const float* h1 = s->hctlX[1];
            int n0 = seg * 16;
            if (seg < RFP / 16) {                // pinned rows
                const float4* wp = reinterpret_cast<const float4*>(s->wpinF);
#pragma unroll 8
                for (int n = n0; n < n0 + 16; ++n) {
                    float4 w = wp[n * 48 + c4];
                    float v0 = h0[n], v1 = h1[n];
                    a0.x += v0 * w.x; a0.y += v0 * w.y; a0.z += v0 * w.z; a0.w += v0 * w.w;
                    a1.x += v1 * w.x; a1.y += v1 * w.y; a1.z += v1 * w.z; a1.w += v1 * w.w;
                }
            } else {                             // streamed rows (L2)
#pragma unroll 8
                for (int n = n0; n < n0 + 16; ++n) {
                    float4 w = __ldg(reinterpret_cast<const float4*>(
                        &Wf[n * OUTW + r * FHALF]) + c4);
                    float v0 = h0[n], v1 = h1[n];
                    a0.x += v0 * w.x; a0.y += v0 * w.y; a0.z += v0 * w.z; a0.w += v0 * w.w;
                    a1.x += v1 * w.x; a1.y += v1 * w.y; a1.z += v1 * w.z; a1.w += v1 * w.w;
                }
            }
            float4* rd = reinterpret_cast<float4*>(s->red);
            rd[seg * 96 + c4]      = a0;
            rd[seg * 96 + 48 + c4] = a1;
        }
        __syncthreads();
        if (tid < 2 * FHALF) {
            int bi = tid / FHALF, v = tid - bi * FHALF;
            float a = s->bf_s[v];
#pragma unroll
            for (int seg = 0; seg < 16; ++seg) a += s->red[(seg * 96 + bi * 48) * 4 + v];
            s->o_half[bi][v] = a;
            if (bi == r) s->o_full[r * FHALF + v] = a;   // my cols of my batch
        }
        __syncthreads();

        // ---- S3: fetch partner's cols of MY batch ----
        cl.sync();
        if (tid < FHALF / 4) {
            const float4* src = (const float4*)cl.map_shared_rank((void*)s->o_half[r], peer);
            reinterpret_cast<float4*>(&s->o_full[peer * FHALF])[tid] = src[tid];
        }
        __syncthreads();

        // ---- P6: emit out / rv / write-key norms ----
        if (tid < OUTW) {
            float a = s->o_full[tid];
            if (tid < DD) {
                out[b * TT * DD + t * DD + tid] = a;
            } else if (tid < CTLW) {
                s->rv[tid - DD] = a;
            } else {
                float ss = a * a;
#pragma unroll
                for (int off = 16; off > 0; off >>= 1) ss += __shfl_xor_sync(0xffffffffu, ss, off);
                if (lane == 0) s->kinvw[(tid - CTLW) >> 5] = rsqrtf(fmaxf(ss, 1e-12f));
            }
        }
        __syncthreads();

        // ---- P7: write addressing (old M; minv valid) ----
        sim_logits(s, &s->o_full[CTLW], s->kinvw, tid);
        __syncthreads();
        if (warp < HH) softmax_blend_row(s, s->wW, warp, lane);
        __syncthreads();

        // ---- P8: M update with pre-Pt writeW ----
        for (int idx = tid; idx < NSLOT * BITS; idx += THREADS) {
            int n = idx >> 5, d = idx & 31;
            float ew = 0.f, aw = 0.f;
#pragma unroll
            for (int h = 0; h < HH; ++h) {
                float w = s->wW[h * NSLOT + n];
                ew += w * s->er_s[h * BITS + d];
                aw += w * s->ad_s[h * BITS + d];
            }
            float mv = s->M[n * MPITCH + d];
            s->M[n * MPITCH + d] = mv * (1.f - ew) + aw;
        }
        __syncthreads();

        // ---- PF: P9 (warps 0-3) | M norms | x prefetch | kinv ----
        if (warp < HH) {
            int h = warp;
            float v[4];
#pragma unroll
            for (int i = 0; i < 4; ++i) {
                int n = lane + i * 32;
                v[i] = s->Wg_s[h * NSLOT + n] * s->hisW[h * NSLOT + n];
            }
            float m = fmaxf(fmaxf(v[0], v[1]), fmaxf(v[2], v[3]));
#pragma unroll
            for (int off = 16; off > 0; off >>= 1) m = fmaxf(m, __shfl_xor_sync(0xffffffffu, m, off));
            float sum = 0.f;
#pragma unroll
            for (int i = 0; i < 4; ++i) { v[i] = __expf(v[i] - m); sum += v[i]; }
#pragma unroll
            for (int off = 16; off > 0; off >>= 1) sum += __shfl_xor_sync(0xffffffffu, sum, off);
            float inv = 1.0f / sum;
#pragma unroll
            for (int i = 0; i < 4; ++i) {
                int n = lane + i * 32;
                float wnew = s->wW[h * NSLOT + n] * (v[i] * inv);
                s->wW[h * NSLOT + n] = wnew;
                s->hisW[h * NSLOT + n] += wnew;
            }
        } else if (tid < 2 * NSLOT) {
            int n = tid - NSLOT;
            const float4* Mr = reinterpret_cast<const float4*>(&s->M[n * MPITCH]);
            float ss = 0.f;
#pragma unroll
            for (int i = 0; i < 8; ++i) {
                float4 v = Mr[i];
                ss += v.x * v.x + v.y * v.y + v.z * v.z + v.w * v.w;
            }
            s->minv[n] = rsqrtf(fmaxf(ss, 1e-12f));
        } else if (tid < 384) {
            int d = tid - 256;
            if (t + 1 < TT) s->ctlX[r][d] = x[b * TT * DD + (t + 1) * DD + d];
        } else if (tid < 384 + HH) {
            int h = tid - 384;
            float ss = 0.f;
#pragma unroll
            for (int k = 0; k < BITS; ++k) { float v = s->rv[h * BITS + k]; ss += v * v; }
            s->kinv[h] = rsqrtf(fmaxf(ss, 1e-12f));
        }
        __syncthreads();
    }
}

extern "C" void kernel_launch(void* const* d_in, const int* in_sizes, int n_in,
                              void* d_out, int out_size)
{
    const float* x       = (const float*)d_in[0];
    const float* beta    = (const float*)d_in[1];
    const float* g       = (const float*)d_in[2];
    const float* erase   = (const float*)d_in[3];
    const float* add     = (const float*)d_in[4];
    const float* Wg      = (const float*)d_in[5];
    const float* M0      = (const float*)d_in[6];
    const float* read0   = (const float*)d_in[7];
    const float* readW0  = (const float*)d_in[8];
    const float* writeW0 = (const float*)d_in[9];
    // d_in[10] = S0   (dead)
    const float* Wc      = (const float*)d_in[11];
    const float* bc      = (const float*)d_in[12];
    const float* Wf      = (const float*)d_in[13];
    const float* bf      = (const float*)d_in[14];
    // d_in[15..17] = Wi, Ui, b_gru (dead)

    (void)in_sizes; (void)n_in; (void)out_size;

    cudaFuncSetAttribute(uic_kernel, cudaFuncAttributeMaxDynamicSharedMemorySize,
                         (int)sizeof(SmemLayout));
    uic_kernel<<<BB, THREADS, sizeof(SmemLayout)>>>(x, beta, g, erase, add, Wg,
                                                    M0, read0, readW0, writeW0,
                                                    Wc, bc, Wf, bf, (float*)d_out);
}

// round 8
// speedup vs baseline: 1.4860x; 1.1686x over previous
#include <cuda_runtime.h>
#include <cooperative_groups.h>

namespace cg = cooperative_groups;

// Problem constants
#define BB    128
#define TT    32
#define DD    128
#define NSLOT 128
#define BITS  32
#define HH    4
#define UU    256
#define HDW   128
#define CTLW  256
#define OUTW  384
#define MPITCH 36
#define THREADS 768
#define CLN   4        // cluster size = batches per cluster
#define CQ    64       // Wc column quarter
#define FQ    96       // Wf column quarter

struct SmemLayout {
    float M[NSLOT * MPITCH];     // 4608
    float ctlX[CLN][CTLW];       // 1024  ctl of all 4 batches (slot bi filled by rank bi)
    float hctlX[CLN][UU];        // 1024  full hidden, all 4 batches (assembled)
    float o_part[CLN][FQ];       // 384   my col-quarter of o, all 4 batches
    float o_full[OUTW];          // 384   full o of MY batch
    float rW[HH * NSLOT];
    float wW[HH * NSLOT];
    float hisW[HH * NSLOT];
    float rv[HDW];
    float minv[NSLOT];
    float kinv[HH];
    float kinvw[HH];
    float beta_s[HH * NSLOT];
    float g_s[HH * NSLOT];
    float Wg_s[HH * NSLOT];
    float er_s[HH * BITS];
    float ad_s[HH * BITS];
    float bc_s[CQ];              // my col-quarter of bc
    float bf_s[FQ];              // my col-quarter of bf
    float red[5120];             // scratch: logits / split-k partials
    float wpinC[256 * CQ];       // 16384  ALL Wc rows, my col-quarter
    float wpinF[256 * FQ];       // 24576  ALL Wf rows, my col-quarter
};
// 57,256 floats = 229,024 bytes <= 232,448 B opt-in

// cosine logits into red[0..511] (tid < 512)
__device__ __forceinline__ void sim_logits(SmemLayout* s, const float* __restrict__ keys,
                                           const float* __restrict__ kinvv, int tid)
{
    if (tid < HH * NSLOT) {
        int h = tid >> 7, n = tid & 127;
        const float4* Mr = reinterpret_cast<const float4*>(&s->M[n * MPITCH]);
        const float4* Kr = reinterpret_cast<const float4*>(&keys[h * BITS]);
        float raw = 0.f;
#pragma unroll
        for (int i = 0; i < 8; ++i) {
            float4 mm = Mr[i];
            float4 kk = Kr[i];
            raw += mm.x * kk.x + mm.y * kk.y + mm.z * kk.z + mm.w * kk.w;
        }
        s->red[tid] = -s->beta_s[tid] * kinvv[h] * s->minv[n] * raw;
    }
}

__device__ __forceinline__ void softmax_blend_row(SmemLayout* s, float* __restrict__ dst,
                                                  int h, int lane)
{
    float v[4];
#pragma unroll
    for (int i = 0; i < 4; ++i) v[i] = s->red[h * NSLOT + lane + i * 32];
    float m = fmaxf(fmaxf(v[0], v[1]), fmaxf(v[2], v[3]));
#pragma unroll
    for (int off = 16; off > 0; off >>= 1) m = fmaxf(m, __shfl_xor_sync(0xffffffffu, m, off));
    float sum = 0.f;
#pragma unroll
    for (int i = 0; i < 4; ++i) { v[i] = __expf(v[i] - m); sum += v[i]; }
#pragma unroll
    for (int off = 16; off > 0; off >>= 1) sum += __shfl_xor_sync(0xffffffffu, sum, off);
    float inv = 1.0f / sum;
#pragma unroll
    for (int i = 0; i < 4; ++i) {
        int n = lane + i * 32;
        float gg = s->g_s[h * NSLOT + n];
        dst[h * NSLOT + n] = gg * (v[i] * inv) + (1.f - gg) * dst[h * NSLOT + n];
    }
}

__global__ __cluster_dims__(CLN, 1, 1) __launch_bounds__(THREADS, 1)
void uic_kernel(const float* __restrict__ x, const float* __restrict__ beta,
                const float* __restrict__ g, const float* __restrict__ erase,
                const float* __restrict__ add, const float* __restrict__ Wg,
                const float* __restrict__ M0, const float* __restrict__ read0,
                const float* __restrict__ readW0, const float* __restrict__ writeW0,
                const float* __restrict__ Wc, const float* __restrict__ bc,
                const float* __restrict__ Wf, const float* __restrict__ bf,
                float* __restrict__ out)
{
    extern __shared__ float smem_raw[];
    SmemLayout* s = reinterpret_cast<SmemLayout*>(smem_raw);
    cg::cluster_group cl = cg::this_cluster();
    const int r   = (int)cl.block_rank();    // 0..3 in cluster; my batch-in-cluster
    const int b   = blockIdx.x;              // my batch (cluster c covers 4c..4c+3)
    const int tid = threadIdx.x;
    const int lane = tid & 31;
    const int warp = tid >> 5;

    // ---------------- init ----------------
    for (int idx = tid; idx < NSLOT * BITS; idx += THREADS) {
        int n = idx >> 5, d = idx & 31;
        s->M[n * MPITCH + d] = M0[b * NSLOT * BITS + idx];
    }
    for (int idx = tid; idx < HH * NSLOT; idx += THREADS) {
        s->rW[idx]     = readW0[b * HH * NSLOT + idx];
        s->wW[idx]     = writeW0[b * HH * NSLOT + idx];
        s->hisW[idx]   = 0.f;
        s->beta_s[idx] = beta[idx];
        s->g_s[idx]    = g[idx];
        s->Wg_s[idx]   = Wg[b * HH * NSLOT + idx];
    }
    for (int idx = tid; idx < HDW; idx += THREADS) {
        s->rv[idx]   = read0[b * HDW + idx];
        s->er_s[idx] = erase[b * HDW + idx];
        s->ad_s[idx] = add[b * HDW + idx];
    }
    for (int idx = tid; idx < CQ; idx += THREADS) s->bc_s[idx] = bc[r * CQ + idx];
    for (int idx = tid; idx < FQ; idx += THREADS) s->bf_s[idx] = bf[r * FQ + idx];
    for (int idx = tid; idx < 256 * CQ; idx += THREADS) {
        int n = idx >> 6, c = idx & (CQ - 1);
        s->wpinC[idx] = Wc[n * UU + r * CQ + c];
    }
    for (int idx = tid; idx < 256 * FQ; idx += THREADS) {
        int n = idx / FQ, c = idx - n * FQ;
        s->wpinF[idx] = Wf[n * OUTW + r * FQ + c];
    }
    __syncthreads();

    // ---------------- prologue: x(t=0), minv, kinv ----------------
    if (tid < DD) {
        s->ctlX[r][tid] = x[b * TT * DD + tid];
    } else if (tid < 2 * NSLOT) {
        int n = tid - NSLOT;
        const float4* Mr = reinterpret_cast<const float4*>(&s->M[n * MPITCH]);
        float ss = 0.f;
#pragma unroll
        for (int i = 0; i < 8; ++i) {
            float4 v = Mr[i];
            ss += v.x * v.x + v.y * v.y + v.z * v.z + v.w * v.w;
        }
        s->minv[n] = rsqrtf(fmaxf(ss, 1e-12f));
    } else if (tid < 2 * NSLOT + HH) {
        int h = tid - 2 * NSLOT;
        float ss = 0.f;
#pragma unroll
        for (int k = 0; k < BITS; ++k) { float v = s->rv[h * BITS + k]; ss += v * v; }
        s->kinv[h] = rsqrtf(fmaxf(ss, 1e-12f));
    }
    __syncthreads();

    for (int t = 0; t < TT; ++t) {
        // ---- P2: read addressing ----
        sim_logits(s, s->rv, s->kinv, tid);
        __syncthreads();
        if (warp < HH) softmax_blend_row(s, s->rW, warp, lane);
        __syncthreads();

        // ---- P3: read_input = rW @ M (float4 on d, 24-way split-k) ----
        {
            int task = tid & 31;            // h*8 + d4
            int seg  = tid >> 5;            // 0..23
            int h = task >> 3, d4 = task & 7;
            int n0 = (128 * seg) / 24, n1 = (128 * (seg + 1)) / 24;
            const float4* M4 = reinterpret_cast<const float4*>(s->M);
            const float* rwh = &s->rW[h * NSLOT];
            float4 a = make_float4(0.f, 0.f, 0.f, 0.f);
            for (int n = n0; n < n1; ++n) {
                float4 mm = M4[n * 9 + d4];
                float w = rwh[n];
                a.x += w * mm.x; a.y += w * mm.y; a.z += w * mm.z; a.w += w * mm.w;
            }
            reinterpret_cast<float4*>(s->red)[seg * 32 + task] = a;
        }
        __syncthreads();
        if (tid < HDW) {
            int h = tid >> 5, d = tid & 31;
            int base = (h * 8 + (d >> 2)) * 4 + (d & 3);
            float a = 0.f;
#pragma unroll
            for (int seg = 0; seg < 24; ++seg) a += s->red[seg * 128 + base];
            s->ctlX[r][DD + tid] = a;
        }
        // ---- S1: all ctls ready cluster-wide; gather peers' ctl ----
        cl.sync();
        if (tid < 192) {
            int p = tid / 64, q = tid & 63;
            int pr = p + (p >= r);
            const float4* src = (const float4*)cl.map_shared_rank((void*)s->ctlX[pr], pr);
            reinterpret_cast<float4*>(s->ctlX[pr])[q] = src[q];
        }
        __syncthreads();

        // ---- P4: hctl col-quarter for ALL 4 batches (Wc pinned) ----
        if (tid < 256) {
            int col4 = tid & 15, seg = tid >> 4;      // 16 segs x 16 rows
            const float4* wp = reinterpret_cast<const float4*>(s->wpinC);
            float4 a[CLN];
#pragma unroll
            for (int bi = 0; bi < CLN; ++bi) a[bi] = make_float4(0.f, 0.f, 0.f, 0.f);
            int n0 = seg * 16;
#pragma unroll 4
            for (int n = n0; n < n0 + 16; ++n) {
                float4 w = wp[n * 16 + col4];
#pragma unroll
                for (int bi = 0; bi < CLN; ++bi) {
                    float v = s->ctlX[bi][n];
                    a[bi].x += v * w.x; a[bi].y += v * w.y;
                    a[bi].z += v * w.z; a[bi].w += v * w.w;
                }
            }
            int slot = (seg * 16 + col4) * 17;
#pragma unroll
            for (int bi = 0; bi < CLN; ++bi) {
                s->red[slot + bi * 4 + 0] = a[bi].x;
                s->red[slot + bi * 4 + 1] = a[bi].y;
                s->red[slot + bi * 4 + 2] = a[bi].z;
                s->red[slot + bi * 4 + 3] = a[bi].w;
            }
        }
        __syncthreads();
        if (tid < 256) {
            int bi = tid >> 6, c = tid & 63;
            int base = (c >> 2) * 17 + bi * 4 + (c & 3);
            float a = s->bc_s[c];
#pragma unroll
            for (int seg = 0; seg < 16; ++seg) a += s->red[seg * 16 * 17 + base];
            s->hctlX[bi][r * CQ + c] = fmaxf(a, 0.f);
        }
        // ---- S2: hctl quarters ready; gather peers' quarters ----
        cl.sync();
        if (tid < 192) {
            int p = tid / 64, q = tid & 63;
            int pr = p + (p >= r);
            int bi = q >> 4, c4 = q & 15;
            int off4 = (bi * UU + pr * CQ) / 4 + c4;
            const float4* src = (const float4*)cl.map_shared_rank((void*)s->hctlX, pr);
            reinterpret_cast<float4*>(s->hctlX)[off4] = src[off4];
        }
        __syncthreads();

        // ---- P5: o col-quarter for ALL 4 batches (Wf pinned) ----
        if (tid < 288) {
            int col4 = tid % 24, seg = tid / 24;      // 12 segs x ~21 rows
            int n0 = (256 * seg) / 12, n1 = (256 * (seg + 1)) / 12;
            const float4* wp = reinterpret_cast<const float4*>(s->wpinF);
            float4 a[CLN];
#pragma unroll
            for (int bi = 0; bi < CLN; ++bi) a[bi] = make_float4(0.f, 0.f, 0.f, 0.f);
            for (int n = n0; n < n1; ++n) {
                float4 w = wp[n * 24 + col4];
#pragma unroll
                for (int bi = 0; bi < CLN; ++bi) {
                    float v = s->hctlX[bi][n];
                    a[bi].x += v * w.x; a[bi].y += v * w.y;
                    a[bi].z += v * w.z; a[bi].w += v * w.w;
                }
            }
            int slot = (seg * 24 + col4) * 17;
#pragma unroll
            for (int bi = 0; bi < CLN; ++bi) {
                s->red[slot + bi * 4 + 0] = a[bi].x;
                s->red[slot + bi * 4 + 1] = a[bi].y;
                s->red[slot + bi * 4 + 2] = a[bi].z;
                s->red[slot + bi * 4 + 3] = a[bi].w;
            }
        }
        __syncthreads();
        if (tid < CLN * FQ) {
            int bi = tid / FQ, c = tid - bi * FQ;
            int base = (c >> 2) * 17 + bi * 4 + (c & 3);
            float a = s->bf_s[c];
#pragma unroll
            for (int seg = 0; seg < 12; ++seg) a += s->red[seg * 24 * 17 + base];
            s->o_part[bi][c] = a;
            if (bi == r) s->o_full[r * FQ + c] = a;
        }
        // ---- S3: o quarters ready; gather MY batch's other quarters ----
        cl.sync();
        if (tid < 72) {
            int p = tid / 24, q = tid % 24;
            int pr = p + (p >= r);
            const float4* src = (const float4*)cl.map_shared_rank((void*)s->o_part[r], pr);
            reinterpret_cast<float4*>(&s->o_full[pr * FQ])[q] = src[q];
        }
        __syncthreads();

        // ---- P6: emit out / rv / write-key norms ----
        if (tid < OUTW) {
            float a = s->o_full[tid];
            if (tid < DD) {
                out[b * TT * DD + t * DD + tid] = a;
            } else if (tid < CTLW) {
                s->rv[tid - DD] = a;
            } else {
                float ss = a * a;
#pragma unroll
                for (int off = 16; off > 0; off >>= 1) ss += __shfl_xor_sync(0xffffffffu, ss, off);
                if (lane == 0) s->kinvw[(tid - CTLW) >> 5] = rsqrtf(fmaxf(ss, 1e-12f));
            }
        }
        __syncthreads();

        // ---- P7: write addressing (old M; minv valid) ----
        sim_logits(s, &s->o_full[CTLW], s->kinvw, tid);
        __syncthreads();
        if (warp < HH) softmax_blend_row(s, s->wW, warp, lane);
        __syncthreads();

        // ---- P8: M update with pre-Pt writeW ----
        for (int idx = tid; idx < NSLOT * BITS; idx += THREADS) {
            int n = idx >> 5, d = idx & 31;
            float ew = 0.f, aw = 0.f;
#pragma unroll
            for (int h = 0; h < HH; ++h) {
                float w = s->wW[h * NSLOT + n];
                ew += w * s->er_s[h * BITS + d];
                aw += w * s->ad_s[h * BITS + d];
            }
            float mv = s->M[n * MPITCH + d];
            s->M[n * MPITCH + d] = mv * (1.f - ew) + aw;
        }
        __syncthreads();

        // ---- PF: P9 (warps 0-3) | M norms | x prefetch | kinv ----
        if (warp < HH) {
            int h = warp;
            float v[4];
#pragma unroll
            for (int i = 0; i < 4; ++i) {
                int n = lane + i * 32;
                v[i] = s->Wg_s[h * NSLOT + n] * s->hisW[h * NSLOT + n];
            }
            float m = fmaxf(fmaxf(v[0], v[1]), fmaxf(v[2], v[3]));
#pragma unroll
            for (int off = 16; off > 0; off >>= 1) m = fmaxf(m, __shfl_xor_sync(0xffffffffu, m, off));
            float sum = 0.f;
#pragma unroll
            for (int i = 0; i < 4; ++i) { v[i] = __expf(v[i] - m); sum += v[i]; }
#pragma unroll
            for (int off = 16; off > 0; off >>= 1) sum += __shfl_xor_sync(0xffffffffu, sum, off);
            float inv = 1.0f / sum;
#pragma unroll
            for (int i = 0; i < 4; ++i) {
                int n = lane + i * 32;
                float wnew = s->wW[h * NSLOT + n] * (v[i] * inv);
                s->wW[h * NSLOT + n] = wnew;
                s->hisW[h * NSLOT + n] += wnew;
            }
        } else if (tid < 2 * NSLOT) {
            int n = tid - NSLOT;
            const float4* Mr = reinterpret_cast<const float4*>(&s->M[n * MPITCH]);
            float ss = 0.f;
#pragma unroll
            for (int i = 0; i < 8; ++i) {
                float4 v = Mr[i];
                ss += v.x * v.x + v.y * v.y + v.z * v.z + v.w * v.w;
            }
            s->minv[n] = rsqrtf(fmaxf(ss, 1e-12f));
        } else if (tid < 384) {
            int d = tid - 256;
            if (t + 1 < TT) s->ctlX[r][d] = x[b * TT * DD + (t + 1) * DD + d];
        } else if (tid < 384 + HH) {
            int h = tid - 384;
            float ss = 0.f;
#pragma unroll
            for (int k = 0; k < BITS; ++k) { float v = s->rv[h * BITS + k]; ss += v * v; }
            s->kinv[h] = rsqrtf(fmaxf(ss, 1e-12f));
        }
        __syncthreads();
    }
}

extern "C" void kernel_launch(void* const* d_in, const int* in_sizes, int n_in,
                              void* d_out, int out_size)
{
    const float* x       = (const float*)d_in[0];
    const float* beta    = (const float*)d_in[1];
    const float* g       = (const float*)d_in[2];
    const float* erase   = (const float*)d_in[3];
    const float* add     = (const float*)d_in[4];
    const float* Wg      = (const float*)d_in[5];
    const float* M0      = (const float*)d_in[6];
    const float* read0   = (const float*)d_in[7];
    const float* readW0  = (const float*)d_in[8];
    const float* writeW0 = (const float*)d_in[9];
    // d_in[10] = S0   (dead)
    const float* Wc      = (const float*)d_in[11];
    const float* bc      = (const float*)d_in[12];
    const float* Wf      = (const float*)d_in[13];
    const float* bf      = (const float*)d_in[14];
    // d_in[15..17] = Wi, Ui, b_gru (dead)

    (void)in_sizes; (void)n_in; (void)out_size;

    cudaFuncSetAttribute(uic_kernel, cudaFuncAttributeMaxDynamicSharedMemorySize,
                         (int)sizeof(SmemLayout));
    uic_kernel<<<BB, THREADS, sizeof(SmemLayout)>>>(x, beta, g, erase, add, Wg,
                                                    M0, read0, readW0, writeW0,
                                                    Wc, bc, Wf, bf, (float*)d_out);
}